// round 15
// baseline (speedup 1.0000x reference)
#include <cuda_runtime.h>
#include <cuda_fp16.h>
#include <stdint.h>
#include <math.h>

// ---------------------------------------------------------------------------
// WaveInterference via warp-level fp16 mma.sync, all GEMMs single-pass fp16:
//   C = A_hi @ B_hi^T (+bias), fp32 accumulate.
// CTA tile 128x256, warp tile 64x64 (smem-bandwidth optimal), BK=64,
// 3-stage cp.async, 1 CTA/SM. QKV projection emits V^T fp16 directly.
// Weights pre-scaled x32 (alpha undoes it). B=4, S=4096, H=1024.
// ---------------------------------------------------------------------------

#define BATCH 4
#define SEQL  4096
#define HID   1024
#define MTOT  (BATCH * SEQL)   // 16384

#define BM 128
#define BN 256
#define BK 64
#define TILE_A   16384             // 128 rows x 128 B
#define TILE_BB  32768             // 256 rows x 128 B
#define NSTAGE   3
#define STAGE_B  (TILE_A + TILE_BB)     // 48 KB
#define SMEM_SZ  (NSTAGE * STAGE_B)     // 147456 B; 1 CTA/SM

#define TP 136                     // transpose smem pitch (halves)

#define WSCALE     32.0f
#define INV_WSCALE 0.03125f

// ---------------------------------------------------------------------------
// Device scratch (no allocs allowed anywhere).
// ---------------------------------------------------------------------------
__device__ __half g_xh[(size_t)MTOT * HID];
__device__ __half g_wh[4][(size_t)HID * HID];     // Wq,Wk,Wv,Wo hi (x32)
__device__ float  g_bias3[3 * HID];               // bq|bk|bv concat
__device__ __half g_qkh[2][(size_t)MTOT * HID];   // Q hi, K hi
__device__ __half g_vth[(size_t)MTOT * HID];      // V^T hi [b][h][s]
__device__ float  g_sf[(size_t)BATCH * SEQL * SEQL];   // scores fp32
__device__ __half g_ph_[(size_t)BATCH * SEQL * SEQL];  // softmax weights hi
__device__ __half g_oh[(size_t)MTOT * HID];       // attention out hi

// ---------------------------------------------------------------------------
// PTX helpers (base-target sm_75/sm_80 features only)
// ---------------------------------------------------------------------------
__device__ __forceinline__ uint32_t smem_u32(const void* p) {
    uint32_t a;
    asm("{ .reg .u64 t; cvta.to.shared.u64 t, %1; cvt.u32.u64 %0, t; }" : "=r"(a) : "l"(p));
    return a;
}
__device__ __forceinline__ void cp16(uint32_t dst, const void* src) {
    asm volatile("cp.async.cg.shared.global [%0], [%1], 16;" :: "r"(dst), "l"(src));
}
#define CP_COMMIT() asm volatile("cp.async.commit_group;" ::: "memory")
#define CP_WAIT0()  asm volatile("cp.async.wait_group 0;" ::: "memory")
#define CP_WAIT1()  asm volatile("cp.async.wait_group 1;" ::: "memory")

__device__ __forceinline__ void ldm_x4(uint32_t* r, uint32_t addr) {
    asm volatile("ldmatrix.sync.aligned.m8n8.x4.shared.b16 {%0,%1,%2,%3}, [%4];"
                 : "=r"(r[0]), "=r"(r[1]), "=r"(r[2]), "=r"(r[3]) : "r"(addr));
}
__device__ __forceinline__ void mma_fp16(float* d, const uint32_t* a, const uint32_t* b) {
    asm volatile(
        "mma.sync.aligned.m16n8k16.row.col.f32.f16.f16.f32 "
        "{%0,%1,%2,%3}, {%4,%5,%6,%7}, {%8,%9}, {%0,%1,%2,%3};"
        : "+f"(d[0]), "+f"(d[1]), "+f"(d[2]), "+f"(d[3])
        : "r"(a[0]), "r"(a[1]), "r"(a[2]), "r"(a[3]), "r"(b[0]), "r"(b[1]));
}
// 128B-row tile swizzle: 16B chunk kg (0..7) XOR row&7. Conflict-free for
// the 8-chunk/row cp.async stores and every ldmatrix 8x8 row group.
__device__ __forceinline__ uint32_t tswz(int row, int kg) {
    return (uint32_t)(row * 128 + ((kg ^ (row & 7)) << 4));
}

// ---------------------------------------------------------------------------
// Single-pass fp16 NT GEMM: C = alpha * (A_hi @ B_hi^T) + bias
//   A[M,K], B[N,K] K-major fp16. CTA 128x256, warp 64x64, BK=64, 3 stages.
//   Per-z output: fp32 if (f32mask>>z)&1; transposed fp16 (V^T) if
//   (vtmask>>z)&1 (M rows = batch*4096+seq); else fp16.
// 256 threads, 8 warps (2m x 4n), fp32 register accumulators (128/thread).
// ---------------------------------------------------------------------------
__global__ __launch_bounds__(256, 1) void mmagemm(
    const __half* __restrict__ Ah, const __half* __restrict__ Bh,
    const float* __restrict__ bias, int biasStride, float alpha,
    float* __restrict__ Cf, __half* __restrict__ Ch, __half* __restrict__ Cvt,
    int K, int N, long long sAB, long long sBB,
    long long sCH, long long sCF, int f32mask, int vtmask)
{
    extern __shared__ char smem[];
    const uint32_t sb = smem_u32(smem);
    const int tid  = threadIdx.x;
    const int lane = tid & 31;
    const int wid  = tid >> 5;
    const int wm   = wid & 1;        // 0..1 -> m offset 64*wm
    const int wn   = wid >> 1;       // 0..3 -> n offset 64*wn
    const int z    = blockIdx.z;
    const int m0   = blockIdx.y * BM;
    const int n0   = blockIdx.x * BN;
    const bool wF32 = (f32mask >> z) & 1;
    const bool wVT  = (vtmask >> z) & 1;

    const __half* srcA = Ah + (long long)z * sAB + (long long)m0 * K;
    const __half* srcB = Bh + (long long)z * sBB + (long long)n0 * K;

    float acc[4][8][4];
#pragma unroll
    for (int i = 0; i < 4; i++)
#pragma unroll
        for (int j = 0; j < 8; j++)
#pragma unroll
            for (int q = 0; q < 4; q++) acc[i][j][q] = 0.0f;

    const int KC = K / BK;

    auto load_stage = [&](int s, int k0) {
        const uint32_t base = sb + s * STAGE_B;
#pragma unroll
        for (int h = 0; h < 4; h++) {          // A: 128 rows x 8 chunks
            const int c = tid + h * 256;
            const int row = c >> 3;
            const int kg  = c & 7;
            cp16(base + tswz(row, kg), srcA + (long long)row * K + k0 + kg * 8);
        }
#pragma unroll
        for (int h = 0; h < 8; h++) {          // B: 256 rows x 8 chunks
            const int c = tid + h * 256;
            const int row = c >> 3;
            const int kg  = c & 7;
            cp16(base + TILE_A + tswz(row, kg), srcB + (long long)row * K + k0 + kg * 8);
        }
        CP_COMMIT();
    };

    load_stage(0, 0);
    load_stage(1, BK);

    for (int c = 0; c < KC; ++c) {
        if (c == KC - 1) CP_WAIT0(); else CP_WAIT1();
        __syncthreads();                 // stage c ready; compute c-1 done
        if (c + 2 < KC) {
            const int s2i = c + 2;
            load_stage(s2i % NSTAGE, s2i * BK);
        }

        const uint32_t st = sb + (c % NSTAGE) * STAGE_B;
#pragma unroll
        for (int ks = 0; ks < 4; ++ks) {   // four k16 steps per BK=64
            uint32_t afh[4][4];
#pragma unroll
            for (int mt = 0; mt < 4; ++mt) {
                const int row = wm * 64 + mt * 16 + (lane & 15);
                const int kg  = ks * 2 + (lane >> 4);
                ldm_x4(afh[mt], st + tswz(row, kg));
            }
#pragma unroll
            for (int p = 0; p < 4; ++p) {
                const int n  = wn * 64 + p * 16 + (lane & 7) + ((lane >> 4) & 1) * 8;
                const int kg = ks * 2 + ((lane >> 3) & 1);
                uint32_t bfh[4];
                ldm_x4(bfh, st + TILE_A + tswz(n, kg));
#pragma unroll
                for (int mt = 0; mt < 4; ++mt) {
#pragma unroll
                    for (int s2 = 0; s2 < 2; ++s2)
                        mma_fp16(acc[mt][p * 2 + s2], afh[mt], bfh + s2 * 2);
                }
            }
        }
    }

    // ---- epilogue ----
    const int lr_base = wm * 64 + (lane >> 2);       // CTA-local row
    const int lc_base = wn * 64 + (lane & 3) * 2;    // CTA-local col

    if (wVT) {
        // Transposed fp16 output: V^T[b][h][s]. Stage smem reused as a
        // 256(hid) x 128(seq) half tile, pitch TP.
        __syncthreads();                 // all warps done reading stages
        __half* smt = (__half*)smem;
#pragma unroll
        for (int mt = 0; mt < 4; ++mt) {
#pragma unroll
            for (int nt = 0; nt < 8; ++nt) {
                const int lr = lr_base + mt * 16;
                const int lc = lc_base + nt * 8;
                float v0 = acc[mt][nt][0] * alpha;
                float v1 = acc[mt][nt][1] * alpha;
                float v2 = acc[mt][nt][2] * alpha;
                float v3 = acc[mt][nt][3] * alpha;
                const float b0 = bias[z * biasStride + n0 + lc];
                const float b1 = bias[z * biasStride + n0 + lc + 1];
                v0 += b0; v1 += b1; v2 += b0; v3 += b1;
                smt[(lc + 0) * TP + lr]     = __float2half_rn(v0);
                smt[(lc + 1) * TP + lr]     = __float2half_rn(v1);
                smt[(lc + 0) * TP + lr + 8] = __float2half_rn(v2);
                smt[(lc + 1) * TP + lr + 8] = __float2half_rn(v3);
            }
        }
        __syncthreads();
        const int batch = m0 >> 12;          // m0 / 4096
        const int s0    = m0 & 4095;
        __half* dst = Cvt + (size_t)batch * HID * SEQL;
#pragma unroll
        for (int j = 0; j < 16; ++j) {
            const int orow = (tid >> 4) + j * 16;     // 0..255 (hid-local)
            const int ocol = (tid & 15) * 8;          // 0..120 (seq-local)
            uint4 v = *(const uint4*)&smt[orow * TP + ocol];
            *(uint4*)&dst[(size_t)(n0 + orow) * SEQL + s0 + ocol] = v;
        }
        return;
    }

#pragma unroll
    for (int mt = 0; mt < 4; ++mt) {
#pragma unroll
        for (int nt = 0; nt < 8; ++nt) {
            const int row = m0 + lr_base + mt * 16;
            const int col = n0 + lc_base + nt * 8;
            float v0 = acc[mt][nt][0] * alpha;
            float v1 = acc[mt][nt][1] * alpha;
            float v2 = acc[mt][nt][2] * alpha;
            float v3 = acc[mt][nt][3] * alpha;
            if (bias) {
                const float b0 = bias[z * biasStride + col];
                const float b1 = bias[z * biasStride + col + 1];
                v0 += b0; v1 += b1; v2 += b0; v3 += b1;
            }
            const long long co1 = (long long)row * N + col;
            const long long co2 = co1 + 8ll * N;
            if (wF32) {
                *(float2*)&Cf[z * sCF + co1] = make_float2(v0, v1);
                *(float2*)&Cf[z * sCF + co2] = make_float2(v2, v3);
            } else {
                *(__half2*)&Ch[z * sCH + co1] =
                    __halves2half2(__float2half_rn(v0), __float2half_rn(v1));
                *(__half2*)&Ch[z * sCH + co2] =
                    __halves2half2(__float2half_rn(v2), __float2half_rn(v3));
            }
        }
    }
}

// ---------------------------------------------------------------------------
// fp32 -> fp16 with scale (one float4 per thread).
// ---------------------------------------------------------------------------
__global__ __launch_bounds__(256) void cvt_h(const float* __restrict__ in,
                                             __half* __restrict__ h, float scale)
{
    const long long i = (long long)blockIdx.x * 256 + threadIdx.x;
    float4 v = ((const float4*)in)[i];
    ((__half2*)h)[2 * i + 0] = __halves2half2(__float2half_rn(v.x * scale),
                                              __float2half_rn(v.y * scale));
    ((__half2*)h)[2 * i + 1] = __halves2half2(__float2half_rn(v.z * scale),
                                              __float2half_rn(v.w * scale));
}

__global__ void concat_bias(const float* __restrict__ bq, const float* __restrict__ bk,
                            const float* __restrict__ bv, float* __restrict__ dst)
{
    const int i = blockIdx.x * 256 + threadIdx.x;
    if (i < HID)            dst[i] = bq[i];
    else if (i < 2 * HID)   dst[i] = bk[i - HID];
    else if (i < 3 * HID)   dst[i] = bv[i - 2 * HID];
}

// ---------------------------------------------------------------------------
// Row softmax over fp32 scores -> fp16 hi weights.
// ---------------------------------------------------------------------------
__global__ __launch_bounds__(256) void softmax_h(const float* __restrict__ S,
                                                 __half* __restrict__ Wh)
{
    const float* row = S + (size_t)blockIdx.x * SEQL;
    __half* rh = Wh + (size_t)blockIdx.x * SEQL;
    const int tid = threadIdx.x;
    __shared__ float red[256];

    float vals[16];
    float lmax = -3.402823e38f;
#pragma unroll
    for (int i = 0; i < 4; ++i) {
        float4 t = *(const float4*)&row[(tid + i * 256) * 4];
        vals[i * 4 + 0] = t.x; vals[i * 4 + 1] = t.y;
        vals[i * 4 + 2] = t.z; vals[i * 4 + 3] = t.w;
        lmax = fmaxf(lmax, fmaxf(fmaxf(t.x, t.y), fmaxf(t.z, t.w)));
    }
    red[tid] = lmax;
    __syncthreads();
#pragma unroll
    for (int s = 128; s > 0; s >>= 1) {
        if (tid < s) red[tid] = fmaxf(red[tid], red[tid + s]);
        __syncthreads();
    }
    const float m = red[0];
    __syncthreads();

    float lsum = 0.0f;
#pragma unroll
    for (int i = 0; i < 16; ++i) { vals[i] = expf(vals[i] - m); lsum += vals[i]; }
    red[tid] = lsum;
    __syncthreads();
#pragma unroll
    for (int s = 128; s > 0; s >>= 1) {
        if (tid < s) red[tid] += red[tid + s];
        __syncthreads();
    }
    const float inv = 1.0f / red[0];

#pragma unroll
    for (int i = 0; i < 4; ++i) {
        const int idx = (tid + i * 256) * 4;
        *(__half2*)&rh[idx + 0] = __halves2half2(
            __float2half_rn(vals[i * 4 + 0] * inv), __float2half_rn(vals[i * 4 + 1] * inv));
        *(__half2*)&rh[idx + 2] = __halves2half2(
            __float2half_rn(vals[i * 4 + 2] * inv), __float2half_rn(vals[i * 4 + 3] * inv));
    }
}

// ---------------------------------------------------------------------------
extern "C" void kernel_launch(void* const* d_in, const int* in_sizes, int n_in,
                              void* d_out, int out_size)
{
    (void)in_sizes; (void)n_in; (void)out_size;
    const float* x  = (const float*)d_in[0];
    const float* Wq = (const float*)d_in[1];
    const float* bq = (const float*)d_in[2];
    const float* Wk = (const float*)d_in[3];
    const float* bk = (const float*)d_in[4];
    const float* Wv = (const float*)d_in[5];
    const float* bv = (const float*)d_in[6];
    const float* Wo = (const float*)d_in[7];
    const float* bo = (const float*)d_in[8];
    float* out = (float*)d_out;

    __half *xh, *wh, *qkh, *vth, *ph, *oh;
    float *sf, *bias3;
    cudaGetSymbolAddress((void**)&xh, g_xh);
    cudaGetSymbolAddress((void**)&wh, g_wh);
    cudaGetSymbolAddress((void**)&bias3, g_bias3);
    cudaGetSymbolAddress((void**)&qkh, g_qkh);
    cudaGetSymbolAddress((void**)&vth, g_vth);
    cudaGetSymbolAddress((void**)&sf, g_sf);
    cudaGetSymbolAddress((void**)&ph, g_ph_);
    cudaGetSymbolAddress((void**)&oh, g_oh);

    cudaFuncSetAttribute(mmagemm, cudaFuncAttributeMaxDynamicSharedMemorySize, SMEM_SZ);

    const size_t WELE = (size_t)HID * HID;
    const long long sQKV = (long long)SEQL * HID;
    const long long sS   = (long long)SEQL * SEQL;
    const long long sPL  = (long long)MTOT * HID;   // plane stride
    const float scl = 0.04419417382415922f;         // 1/sqrt(512)

    // ---- input conversions (all single-plane fp16; weights x32) ----
    cvt_h<<<(MTOT * (size_t)HID) / 4 / 256, 256>>>(x, xh, 1.0f);
    cvt_h<<<WELE / 4 / 256, 256>>>(Wq, wh + 0 * WELE, WSCALE);
    cvt_h<<<WELE / 4 / 256, 256>>>(Wk, wh + 1 * WELE, WSCALE);
    cvt_h<<<WELE / 4 / 256, 256>>>(Wv, wh + 2 * WELE, WSCALE);
    cvt_h<<<WELE / 4 / 256, 256>>>(Wo, wh + 3 * WELE, WSCALE);
    concat_bias<<<(3 * HID + 255) / 256, 256>>>(bq, bk, bv, bias3);

    // ---- merged QKV projection: z=0 -> Q hi, z=1 -> K hi, z=2 -> V^T hi ----
    mmagemm<<<dim3(HID / BN, MTOT / BM, 3), 256, SMEM_SZ>>>(
        xh, wh, bias3, HID, INV_WSCALE,
        nullptr, qkh, vth,
        HID, HID, /*sAB*/0, /*sBB*/(long long)WELE,
        /*sCH*/sPL, /*sCF*/0, /*f32mask*/0, /*vtmask*/0b100);

    // ---- scores = Q K^T / sqrt(512) (fp32 out, per-batch z) ----
    mmagemm<<<dim3(SEQL / BN, SEQL / BM, BATCH), 256, SMEM_SZ>>>(
        qkh, qkh + sPL, nullptr, 0, scl,
        sf, nullptr, nullptr,
        HID, SEQL, sQKV, sQKV, 0, sS, 0xF, 0);

    // ---- softmax -> fp16 hi weights ----
    softmax_h<<<BATCH * SEQL, 256>>>(sf, ph);

    // ---- O = weights @ V^T_hi, fp16 hi out ----
    mmagemm<<<dim3(HID / BN, SEQL / BM, BATCH), 256, SMEM_SZ>>>(
        ph, vth, nullptr, 0, 1.0f,
        nullptr, oh, nullptr,
        SEQL, HID, sS, sQKV, sQKV, 0, 0, 0);

    // ---- out = O @ Wo^T_hi + bo (fp32 out) ----
    mmagemm<<<dim3(HID / BN, MTOT / BM, 1), 256, SMEM_SZ>>>(
        oh, wh + 3 * WELE, bo, 0, INV_WSCALE,
        out, nullptr, nullptr,
        HID, HID, 0, 0, 0, 0, 1, 0);
}

// round 17
// speedup vs baseline: 1.1699x; 1.1699x over previous
#include <cuda_runtime.h>
#include <cuda_fp16.h>
#include <stdint.h>
#include <math.h>

// ---------------------------------------------------------------------------
// WaveInterference via warp-level fp16 mma.sync, all GEMMs single-pass fp16:
//   C = A_hi @ B_hi^T (+bias), fp32 accumulate. BK=64, 3-stage cp.async,
//   CTA 128x128, warp 32x64, 2 CTAs/SM (R14 config — register-file optimal).
// QKV projection writes V^T fp16 directly via smem transpose (z=2).
// Weights pre-scaled x32 (alpha undoes it). B=4, S=4096, H=1024.
// ---------------------------------------------------------------------------

#define BATCH 4
#define SEQL  4096
#define HID   1024
#define MTOT  (BATCH * SEQL)   // 16384

#define BM 128
#define BN 128
#define BK 64
#define TILE_B   16384             // 128 rows x 128 B (64 fp16)
#define NSTAGE   3
#define STAGE_B  (2 * TILE_B)      // A, B tiles = 32 KB
#define SMEM_SZ  (NSTAGE * STAGE_B) // 98304 B; x2 CTAs = 192 KB <= 228 KB

#define TP 136                     // transpose smem pitch (halves)

#define WSCALE     32.0f
#define INV_WSCALE 0.03125f

// ---------------------------------------------------------------------------
// Device scratch (no allocs allowed anywhere).
// ---------------------------------------------------------------------------
__device__ __half g_xh[(size_t)MTOT * HID];
__device__ __half g_wh[4][(size_t)HID * HID];     // Wq,Wk,Wv,Wo hi (x32)
__device__ float  g_bias3[3 * HID];               // bq|bk|bv concat
__device__ __half g_qkh[2][(size_t)MTOT * HID];   // Q hi, K hi
__device__ __half g_vth[(size_t)MTOT * HID];      // V^T hi [b][h][s]
__device__ float  g_sf[(size_t)BATCH * SEQL * SEQL];   // scores fp32
__device__ __half g_ph_[(size_t)BATCH * SEQL * SEQL];  // softmax weights hi
__device__ __half g_oh[(size_t)MTOT * HID];       // attention out hi

// ---------------------------------------------------------------------------
// PTX helpers (base-target sm_75/sm_80 features only)
// ---------------------------------------------------------------------------
__device__ __forceinline__ uint32_t smem_u32(const void* p) {
    uint32_t a;
    asm("{ .reg .u64 t; cvta.to.shared.u64 t, %1; cvt.u32.u64 %0, t; }" : "=r"(a) : "l"(p));
    return a;
}
__device__ __forceinline__ void cp16(uint32_t dst, const void* src) {
    asm volatile("cp.async.cg.shared.global [%0], [%1], 16;" :: "r"(dst), "l"(src));
}
#define CP_COMMIT() asm volatile("cp.async.commit_group;" ::: "memory")
#define CP_WAIT0()  asm volatile("cp.async.wait_group 0;" ::: "memory")
#define CP_WAIT1()  asm volatile("cp.async.wait_group 1;" ::: "memory")

__device__ __forceinline__ void ldm_x4(uint32_t* r, uint32_t addr) {
    asm volatile("ldmatrix.sync.aligned.m8n8.x4.shared.b16 {%0,%1,%2,%3}, [%4];"
                 : "=r"(r[0]), "=r"(r[1]), "=r"(r[2]), "=r"(r[3]) : "r"(addr));
}
__device__ __forceinline__ void mma_fp16(float* d, const uint32_t* a, const uint32_t* b) {
    asm volatile(
        "mma.sync.aligned.m16n8k16.row.col.f32.f16.f16.f32 "
        "{%0,%1,%2,%3}, {%4,%5,%6,%7}, {%8,%9}, {%0,%1,%2,%3};"
        : "+f"(d[0]), "+f"(d[1]), "+f"(d[2]), "+f"(d[3])
        : "r"(a[0]), "r"(a[1]), "r"(a[2]), "r"(a[3]), "r"(b[0]), "r"(b[1]));
}
// 128B-row tile swizzle: 16B chunk kg (0..7) XOR row&7. Conflict-free for
// the 8-chunk/row cp.async stores and every ldmatrix 8x8 row group.
__device__ __forceinline__ uint32_t tswz(int row, int kg) {
    return (uint32_t)(row * 128 + ((kg ^ (row & 7)) << 4));
}

// ---------------------------------------------------------------------------
// Single-pass fp16 NT GEMM: C = alpha * (A_hi @ B_hi^T) + bias
//   A[M,K], B[N,K] K-major fp16. 3-stage cp.async pipeline, BK=64.
//   Per-z output: fp32 if (f32mask>>z)&1; transposed fp16 (V^T) if
//   (vtmask>>z)&1 (M rows interpreted as batch*4096+seq); else fp16.
// 256 threads, 8 warps (4m x 2n), warp tile 32x64, fp32 register accumulators.
// ---------------------------------------------------------------------------
__global__ __launch_bounds__(256, 2) void mmagemm(
    const __half* __restrict__ Ah, const __half* __restrict__ Bh,
    const float* __restrict__ bias, int biasStride, float alpha,
    float* __restrict__ Cf, __half* __restrict__ Ch, __half* __restrict__ Cvt,
    int K, int N, long long sAB, long long sBB,
    long long sCH, long long sCF, int f32mask, int vtmask)
{
    extern __shared__ char smem[];
    const uint32_t sb = smem_u32(smem);
    const int tid  = threadIdx.x;
    const int lane = tid & 31;
    const int wid  = tid >> 5;
    const int wm   = wid & 3;
    const int wn   = wid >> 2;
    const int z    = blockIdx.z;
    const int m0   = blockIdx.y * BM;
    const int n0   = blockIdx.x * BN;
    const bool wF32 = (f32mask >> z) & 1;
    const bool wVT  = (vtmask >> z) & 1;

    const __half* srcA = Ah + (long long)z * sAB + (long long)m0 * K;
    const __half* srcB = Bh + (long long)z * sBB + (long long)n0 * K;

    float acc[2][8][4];
#pragma unroll
    for (int i = 0; i < 2; i++)
#pragma unroll
        for (int j = 0; j < 8; j++)
#pragma unroll
            for (int q = 0; q < 4; q++) acc[i][j][q] = 0.0f;

    const int KC = K / BK;

    auto load_stage = [&](int s, int k0) {
        const uint32_t base = sb + s * STAGE_B;
#pragma unroll
        for (int h = 0; h < 4; h++) {
            const int c = tid + h * 256;     // 0..1023
            const int row = c >> 3;
            const int kg  = c & 7;
            const uint32_t so = tswz(row, kg);
            const long long go = (long long)row * K + k0 + kg * 8;
            cp16(base + so, srcA + go);
            cp16(base + TILE_B + so, srcB + go);
        }
        CP_COMMIT();
    };

    load_stage(0, 0);
    load_stage(1, BK);

    for (int c = 0; c < KC; ++c) {
        if (c == KC - 1) CP_WAIT0(); else CP_WAIT1();
        __syncthreads();                 // stage c ready; compute c-1 done
        if (c + 2 < KC) {
            const int s2i = c + 2;
            load_stage(s2i % NSTAGE, s2i * BK);
        }

        const uint32_t st = sb + (c % NSTAGE) * STAGE_B;
#pragma unroll
        for (int ks = 0; ks < 4; ++ks) {   // four k16 steps per BK=64
            uint32_t afh[2][4];
#pragma unroll
            for (int mt = 0; mt < 2; ++mt) {
                const int row = wm * 32 + mt * 16 + (lane & 15);
                const int kg  = ks * 2 + (lane >> 4);
                ldm_x4(afh[mt], st + tswz(row, kg));
            }
#pragma unroll
            for (int p = 0; p < 4; ++p) {
                const int n  = wn * 64 + p * 16 + (lane & 7) + ((lane >> 4) & 1) * 8;
                const int kg = ks * 2 + ((lane >> 3) & 1);
                uint32_t bfh[4];
                ldm_x4(bfh, st + TILE_B + tswz(n, kg));
#pragma unroll
                for (int mt = 0; mt < 2; ++mt) {
#pragma unroll
                    for (int s2 = 0; s2 < 2; ++s2)
                        mma_fp16(acc[mt][p * 2 + s2], afh[mt], bfh + s2 * 2);
                }
            }
        }
    }

    // ---- epilogue ----
    const int lr_base = wm * 32 + (lane >> 2);       // CTA-local row
    const int lc_base = wn * 64 + (lane & 3) * 2;    // CTA-local col

    if (wVT) {
        // Transposed fp16 output: V^T[b][h][s]. Stage smem is reused as a
        // 128x128 half tile with pitch TP (conflict-managed).
        __syncthreads();                 // all warps done reading stages
        __half* smt = (__half*)smem;
#pragma unroll
        for (int mt = 0; mt < 2; ++mt) {
#pragma unroll
            for (int nt = 0; nt < 8; ++nt) {
                const int lr = lr_base + mt * 16;
                const int lc = lc_base + nt * 8;
                float v0 = acc[mt][nt][0] * alpha;
                float v1 = acc[mt][nt][1] * alpha;
                float v2 = acc[mt][nt][2] * alpha;
                float v3 = acc[mt][nt][3] * alpha;
                const float b0 = bias[z * biasStride + n0 + lc];
                const float b1 = bias[z * biasStride + n0 + lc + 1];
                v0 += b0; v1 += b1; v2 += b0; v3 += b1;
                smt[(lc + 0) * TP + lr]     = __float2half_rn(v0);
                smt[(lc + 1) * TP + lr]     = __float2half_rn(v1);
                smt[(lc + 0) * TP + lr + 8] = __float2half_rn(v2);
                smt[(lc + 1) * TP + lr + 8] = __float2half_rn(v3);
            }
        }
        __syncthreads();
        const int batch = m0 >> 12;          // m0 / 4096
        const int s0    = m0 & 4095;
        __half* dst = Cvt + (size_t)batch * HID * SEQL;
#pragma unroll
        for (int j = 0; j < 8; ++j) {
            const int orow = (tid >> 4) + j * 16;     // 0..127 (hid-local)
            const int ocol = (tid & 15) * 8;          // 0..120 (seq-local)
            uint4 v = *(const uint4*)&smt[orow * TP + ocol];
            *(uint4*)&dst[(size_t)(n0 + orow) * SEQL + s0 + ocol] = v;
        }
        return;
    }

#pragma unroll
    for (int mt = 0; mt < 2; ++mt) {
#pragma unroll
        for (int nt = 0; nt < 8; ++nt) {
            const int row = m0 + lr_base + mt * 16;
            const int col = n0 + lc_base + nt * 8;
            float v0 = acc[mt][nt][0] * alpha;
            float v1 = acc[mt][nt][1] * alpha;
            float v2 = acc[mt][nt][2] * alpha;
            float v3 = acc[mt][nt][3] * alpha;
            if (bias) {
                const float b0 = bias[z * biasStride + col];
                const float b1 = bias[z * biasStride + col + 1];
                v0 += b0; v1 += b1; v2 += b0; v3 += b1;
            }
            const long long co1 = (long long)row * N + col;
            const long long co2 = co1 + 8ll * N;
            if (wF32) {
                *(float2*)&Cf[z * sCF + co1] = make_float2(v0, v1);
                *(float2*)&Cf[z * sCF + co2] = make_float2(v2, v3);
            } else {
                *(__half2*)&Ch[z * sCH + co1] =
                    __halves2half2(__float2half_rn(v0), __float2half_rn(v1));
                *(__half2*)&Ch[z * sCH + co2] =
                    __halves2half2(__float2half_rn(v2), __float2half_rn(v3));
            }
        }
    }
}

// ---------------------------------------------------------------------------
// Merged prologue: converts x (fp16), 4 weights (fp16 x32), concats bias.
// Block ranges: [0,16384) x | [16384,20480) weights | [20480,20492) bias.
// ---------------------------------------------------------------------------
#define NBX 16384
#define NBW 1024
__global__ __launch_bounds__(256) void convert_all(
    const float* __restrict__ x,
    const float* __restrict__ Wq, const float* __restrict__ Wk,
    const float* __restrict__ Wv, const float* __restrict__ Wo,
    const float* __restrict__ bq, const float* __restrict__ bk,
    const float* __restrict__ bv,
    __half* __restrict__ xh, __half* __restrict__ wh, float* __restrict__ bias3)
{
    const int b = blockIdx.x;
    if (b < NBX) {
        const long long i = (long long)b * 256 + threadIdx.x;
        float4 v = ((const float4*)x)[i];
        ((__half2*)xh)[2 * i + 0] = __halves2half2(__float2half_rn(v.x), __float2half_rn(v.y));
        ((__half2*)xh)[2 * i + 1] = __halves2half2(__float2half_rn(v.z), __float2half_rn(v.w));
    } else if (b < NBX + 4 * NBW) {
        const int w = (b - NBX) >> 10;
        const float* src = (w == 0) ? Wq : (w == 1) ? Wk : (w == 2) ? Wv : Wo;
        __half* dst = wh + (size_t)w * HID * HID;
        const long long i = (long long)((b - NBX) & (NBW - 1)) * 256 + threadIdx.x;
        float4 v = ((const float4*)src)[i];
        ((__half2*)dst)[2 * i + 0] = __halves2half2(__float2half_rn(v.x * WSCALE),
                                                    __float2half_rn(v.y * WSCALE));
        ((__half2*)dst)[2 * i + 1] = __halves2half2(__float2half_rn(v.z * WSCALE),
                                                    __float2half_rn(v.w * WSCALE));
    } else {
        const int i = (b - NBX - 4 * NBW) * 256 + threadIdx.x;
        if (i < HID)            bias3[i] = bq[i];
        else if (i < 2 * HID)   bias3[i] = bk[i - HID];
        else if (i < 3 * HID)   bias3[i] = bv[i - 2 * HID];
    }
}

// ---------------------------------------------------------------------------
// Row softmax over fp32 scores -> fp16 hi weights.
// ---------------------------------------------------------------------------
__global__ __launch_bounds__(256) void softmax_h(const float* __restrict__ S,
                                                 __half* __restrict__ Wh)
{
    const float* row = S + (size_t)blockIdx.x * SEQL;
    __half* rh = Wh + (size_t)blockIdx.x * SEQL;
    const int tid = threadIdx.x;
    __shared__ float red[256];

    float vals[16];
    float lmax = -3.402823e38f;
#pragma unroll
    for (int i = 0; i < 4; ++i) {
        float4 t = *(const float4*)&row[(tid + i * 256) * 4];
        vals[i * 4 + 0] = t.x; vals[i * 4 + 1] = t.y;
        vals[i * 4 + 2] = t.z; vals[i * 4 + 3] = t.w;
        lmax = fmaxf(lmax, fmaxf(fmaxf(t.x, t.y), fmaxf(t.z, t.w)));
    }
    red[tid] = lmax;
    __syncthreads();
#pragma unroll
    for (int s = 128; s > 0; s >>= 1) {
        if (tid < s) red[tid] = fmaxf(red[tid], red[tid + s]);
        __syncthreads();
    }
    const float m = red[0];
    __syncthreads();

    float lsum = 0.0f;
#pragma unroll
    for (int i = 0; i < 16; ++i) { vals[i] = __expf(vals[i] - m); lsum += vals[i]; }
    red[tid] = lsum;
    __syncthreads();
#pragma unroll
    for (int s = 128; s > 0; s >>= 1) {
        if (tid < s) red[tid] += red[tid + s];
        __syncthreads();
    }
    const float inv = 1.0f / red[0];

#pragma unroll
    for (int i = 0; i < 4; ++i) {
        const int idx = (tid + i * 256) * 4;
        *(__half2*)&rh[idx + 0] = __halves2half2(
            __float2half_rn(vals[i * 4 + 0] * inv), __float2half_rn(vals[i * 4 + 1] * inv));
        *(__half2*)&rh[idx + 2] = __halves2half2(
            __float2half_rn(vals[i * 4 + 2] * inv), __float2half_rn(vals[i * 4 + 3] * inv));
    }
}

// ---------------------------------------------------------------------------
extern "C" void kernel_launch(void* const* d_in, const int* in_sizes, int n_in,
                              void* d_out, int out_size)
{
    (void)in_sizes; (void)n_in; (void)out_size;
    const float* x  = (const float*)d_in[0];
    const float* Wq = (const float*)d_in[1];
    const float* bq = (const float*)d_in[2];
    const float* Wk = (const float*)d_in[3];
    const float* bk = (const float*)d_in[4];
    const float* Wv = (const float*)d_in[5];
    const float* bv = (const float*)d_in[6];
    const float* Wo = (const float*)d_in[7];
    const float* bo = (const float*)d_in[8];
    float* out = (float*)d_out;

    __half *xh, *wh, *qkh, *vth, *ph, *oh;
    float *sf, *bias3;
    cudaGetSymbolAddress((void**)&xh, g_xh);
    cudaGetSymbolAddress((void**)&wh, g_wh);
    cudaGetSymbolAddress((void**)&bias3, g_bias3);
    cudaGetSymbolAddress((void**)&qkh, g_qkh);
    cudaGetSymbolAddress((void**)&vth, g_vth);
    cudaGetSymbolAddress((void**)&sf, g_sf);
    cudaGetSymbolAddress((void**)&ph, g_ph_);
    cudaGetSymbolAddress((void**)&oh, g_oh);

    cudaFuncSetAttribute(mmagemm, cudaFuncAttributeMaxDynamicSharedMemorySize, SMEM_SZ);

    const size_t WELE = (size_t)HID * HID;
    const long long sQKV = (long long)SEQL * HID;
    const long long sS   = (long long)SEQL * SEQL;
    const long long sPL  = (long long)MTOT * HID;   // plane stride
    const float scl = 0.04419417382415922f;         // 1/sqrt(512)

    // ---- merged input conversions (single launch) ----
    convert_all<<<NBX + 4 * NBW + 12, 256>>>(x, Wq, Wk, Wv, Wo, bq, bk, bv,
                                             xh, wh, bias3);

    // ---- merged QKV projection: z=0 -> Q hi, z=1 -> K hi, z=2 -> V^T hi ----
    mmagemm<<<dim3(HID / BN, MTOT / BM, 3), 256, SMEM_SZ>>>(
        xh, wh, bias3, HID, INV_WSCALE,
        nullptr, qkh, vth,
        HID, HID, /*sAB*/0, /*sBB*/(long long)WELE,
        /*sCH*/sPL, /*sCF*/0, /*f32mask*/0, /*vtmask*/0b100);

    // ---- scores = Q K^T / sqrt(512) (fp32 out, per-batch z) ----
    mmagemm<<<dim3(SEQL / BN, SEQL / BM, BATCH), 256, SMEM_SZ>>>(
        qkh, qkh + sPL, nullptr, 0, scl,
        sf, nullptr, nullptr,
        HID, SEQL, sQKV, sQKV, 0, sS, 0xF, 0);

    // ---- softmax -> fp16 hi weights ----
    softmax_h<<<BATCH * SEQL, 256>>>(sf, ph);

    // ---- O = weights @ V^T_hi, fp16 hi out ----
    mmagemm<<<dim3(HID / BN, SEQL / BM, BATCH), 256, SMEM_SZ>>>(
        ph, vth, nullptr, 0, 1.0f,
        nullptr, oh, nullptr,
        SEQL, HID, sS, sQKV, sQKV, 0, 0, 0);

    // ---- out = O @ Wo^T_hi + bo (fp32 out) ----
    mmagemm<<<dim3(HID / BN, MTOT / BM, 1), 256, SMEM_SZ>>>(
        oh, wh + 3 * WELE, bo, 0, INV_WSCALE,
        out, nullptr, nullptr,
        HID, HID, 0, 0, 0, 0, 1, 0);
}